// round 2
// baseline (speedup 1.0000x reference)
#include <cuda_runtime.h>
#include <math.h>

// RippleNet fused kernel, GB300 sm_103a
// H=2, B=2048, M=64, D=16, N_ENT=500000, N_REL=32
// inputs (metadata order): items[B] i32, heads[H,B,M] i32, relations[H,B,M] i32,
//                          tails[H,B,M] i32, ent_emb[N_ENT,16] f32, rel_emb[32,16,16] f32
// output: predicts[B] f32

#define RN_H 2
#define RN_B 2048
#define RN_M 64
#define RN_D 16
#define RN_NREL 32

__global__ __launch_bounds__(128, 8)
void ripple_kernel(const int* __restrict__ items,
                   const int* __restrict__ heads,
                   const int* __restrict__ rels,
                   const int* __restrict__ tails,
                   const float* __restrict__ ent,
                   const float* __restrict__ rel,
                   float* __restrict__ out)
{
    const int b    = blockIdx.x;
    const int tid  = threadIdx.x;        // 0..127
    const int lane = tid & 31;
    const int warp = tid >> 5;           // 0..3
    const int h    = tid >> 6;           // 0..1 (warps 0,1 -> h=0; 2,3 -> h=1)
    const int m    = tid & 63;

    __shared__ float s_item[RN_D];
    __shared__ float s_v[RN_NREL][RN_D + 1];  // +1 pad: kill stride-16 bank conflicts
    __shared__ float s_red[4];                // per-warp softmax scalars
    __shared__ float s_part[4][RN_D];         // per-warp partial user_rep
    __shared__ float s_fin[RN_D];

    // ---- load item embedding (16 threads) ----
    if (tid < RN_D) {
        const int it = items[b];
        s_item[tid] = ent[(size_t)it * RN_D + tid];
    }
    __syncthreads();

    // ---- v[r][j] = sum_i item[i] * R[r][i][j]  (512 entries, 4 per thread) ----
    // rel_emb is 32KB total -> L1-resident per SM after first block touches it.
    #pragma unroll
    for (int e = tid; e < RN_NREL * RN_D; e += 128) {
        const int r = e >> 4;
        const int j = e & 15;
        const float* Rp = rel + r * RN_D * RN_D + j;
        float acc = 0.f;
        #pragma unroll
        for (int i = 0; i < RN_D; i++)
            acc = fmaf(s_item[i], __ldg(Rp + i * RN_D), acc);
        s_v[r][j] = acc;
    }
    __syncthreads();

    // ---- per-(h,m) logit = v[rel] . head_e ----
    const int gidx = (h * RN_B + b) * RN_M + m;
    const int hidx = heads[gidx];
    const int ridx = rels[gidx];
    const int tidx = tails[gidx];

    const float4* hp = (const float4*)(ent + (size_t)hidx * RN_D);
    float4 h0 = __ldg(hp + 0);
    float4 h1 = __ldg(hp + 1);
    float4 h2 = __ldg(hp + 2);
    float4 h3 = __ldg(hp + 3);

    const float* vp = s_v[ridx];
    float logit = 0.f;
    logit = fmaf(vp[0],  h0.x, logit); logit = fmaf(vp[1],  h0.y, logit);
    logit = fmaf(vp[2],  h0.z, logit); logit = fmaf(vp[3],  h0.w, logit);
    logit = fmaf(vp[4],  h1.x, logit); logit = fmaf(vp[5],  h1.y, logit);
    logit = fmaf(vp[6],  h1.z, logit); logit = fmaf(vp[7],  h1.w, logit);
    logit = fmaf(vp[8],  h2.x, logit); logit = fmaf(vp[9],  h2.y, logit);
    logit = fmaf(vp[10], h2.z, logit); logit = fmaf(vp[11], h2.w, logit);
    logit = fmaf(vp[12], h3.x, logit); logit = fmaf(vp[13], h3.y, logit);
    logit = fmaf(vp[14], h3.z, logit); logit = fmaf(vp[15], h3.w, logit);

    // ---- softmax over m (64 values = 2 warps per h) ----
    float mx = logit;
    #pragma unroll
    for (int o = 16; o; o >>= 1)
        mx = fmaxf(mx, __shfl_xor_sync(0xFFFFFFFFu, mx, o));
    if (lane == 0) s_red[warp] = mx;
    __syncthreads();
    mx = fmaxf(s_red[h * 2], s_red[h * 2 + 1]);

    float p = __expf(logit - mx);
    float sm = p;
    #pragma unroll
    for (int o = 16; o; o >>= 1)
        sm += __shfl_xor_sync(0xFFFFFFFFu, sm, o);
    __syncthreads();                 // protect s_red reuse
    if (lane == 0) s_red[warp] = sm;
    __syncthreads();
    sm = s_red[h * 2] + s_red[h * 2 + 1];
    const float pi = p / sm;

    // ---- weighted tail aggregation: user_rep[d] = sum_{h,m} pi * tail[d] ----
    const float4* tp = (const float4*)(ent + (size_t)tidx * RN_D);
    float4 t0 = __ldg(tp + 0);
    float4 t1 = __ldg(tp + 1);
    float4 t2 = __ldg(tp + 2);
    float4 t3 = __ldg(tp + 3);

    float t[RN_D];
    t[0]  = pi * t0.x; t[1]  = pi * t0.y; t[2]  = pi * t0.z; t[3]  = pi * t0.w;
    t[4]  = pi * t1.x; t[5]  = pi * t1.y; t[6]  = pi * t1.z; t[7]  = pi * t1.w;
    t[8]  = pi * t2.x; t[9]  = pi * t2.y; t[10] = pi * t2.z; t[11] = pi * t2.w;
    t[12] = pi * t3.x; t[13] = pi * t3.y; t[14] = pi * t3.z; t[15] = pi * t3.w;

    #pragma unroll
    for (int o = 16; o; o >>= 1) {
        #pragma unroll
        for (int d = 0; d < RN_D; d++)
            t[d] += __shfl_xor_sync(0xFFFFFFFFu, t[d], o);
    }
    if (lane == 0) {
        #pragma unroll
        for (int d = 0; d < RN_D; d++) s_part[warp][d] = t[d];
    }
    __syncthreads();

    // ---- final dot + sigmoid ----
    if (tid < RN_D) {
        const float u = s_part[0][tid] + s_part[1][tid]
                      + s_part[2][tid] + s_part[3][tid];
        s_fin[tid] = u * s_item[tid];
    }
    __syncthreads();
    if (tid == 0) {
        float s = 0.f;
        #pragma unroll
        for (int d = 0; d < RN_D; d++) s += s_fin[d];
        out[b] = 1.f / (1.f + __expf(-s));
    }
}

extern "C" void kernel_launch(void* const* d_in, const int* in_sizes, int n_in,
                              void* d_out, int out_size)
{
    const int*   items = (const int*)  d_in[0];
    const int*   heads = (const int*)  d_in[1];
    const int*   rels  = (const int*)  d_in[2];
    const int*   tails = (const int*)  d_in[3];
    const float* ent   = (const float*)d_in[4];
    const float* rel   = (const float*)d_in[5];
    float*       out   = (float*)      d_out;

    ripple_kernel<<<RN_B, 128>>>(items, heads, rels, tails, ent, rel, out);
}

// round 3
// speedup vs baseline: 1.4786x; 1.4786x over previous
#include <cuda_runtime.h>
#include <math.h>

// RippleNet fused, GB300 sm_103a
// H=2, B=2048, M=64, D=16, N_ENT=500000, N_REL=32
#define RN_H 2
#define RN_B 2048
#define RN_M 64
#define RN_D 16
#define RN_NREL 32
#define RN_BPB 8   // batches per block in vprep

// scratch: V[b][r][j] = sum_i item[b][i] * R[r][i][j]   (2048*32*16 floats = 4MB)
__device__ float g_V[RN_B * RN_NREL * RN_D];

// ---------------- Kernel 1: V precompute ----------------
// grid = B/RN_BPB = 256 blocks, 128 threads.
// thread = (r, j4): r = tid>>2 (0..31), j4 = tid&3. R column cached in 16 float4 regs.
__global__ __launch_bounds__(128)
void vprep_kernel(const int* __restrict__ items,
                  const float* __restrict__ ent,
                  const float* __restrict__ rel)
{
    const int tid = threadIdx.x;
    const int r   = tid >> 2;
    const int j4  = tid & 3;

    // register-cache R[r][i][j4*4 .. j4*4+3] for i = 0..15
    float4 Rreg[RN_D];
    #pragma unroll
    for (int i = 0; i < RN_D; i++)
        Rreg[i] = __ldg((const float4*)(rel + (r * RN_D + i) * RN_D) + j4);

    __shared__ float s_it[RN_BPB][RN_D];
    const int b0 = blockIdx.x * RN_BPB;
    {
        const int row = tid >> 4;   // 0..7
        const int col = tid & 15;
        const int it  = items[b0 + row];
        s_it[row][col] = __ldg(ent + (size_t)it * RN_D + col);
    }
    __syncthreads();

    #pragma unroll
    for (int bb = 0; bb < RN_BPB; bb++) {
        float4 acc = make_float4(0.f, 0.f, 0.f, 0.f);
        #pragma unroll
        for (int i = 0; i < RN_D; i++) {
            const float s = s_it[bb][i];     // shared broadcast, conflict-free
            acc.x = fmaf(s, Rreg[i].x, acc.x);
            acc.y = fmaf(s, Rreg[i].y, acc.y);
            acc.z = fmaf(s, Rreg[i].z, acc.z);
            acc.w = fmaf(s, Rreg[i].w, acc.w);
        }
        // offset (tid>>2)*16 + (tid&3)*4 == tid*4  -> fully coalesced STG.128
        *((float4*)(g_V + (size_t)(b0 + bb) * (RN_NREL * RN_D)) + tid) = acc;
    }
}

// ---------------- Kernel 2: main ----------------
// 1 block per b, 128 threads. Thread owns memory mem = tid (h = tid>>6, m = tid&63).
// Gathers done cooperatively: 4-lane groups split each 64B entity row into 16B quarters.
__global__ __launch_bounds__(128, 8)
void ripple_main(const int* __restrict__ items,
                 const int* __restrict__ heads,
                 const int* __restrict__ rels,
                 const int* __restrict__ tails,
                 const float* __restrict__ ent,
                 float* __restrict__ out)
{
    const int b    = blockIdx.x;
    const int tid  = threadIdx.x;
    const int lane = tid & 31;
    const int warp = tid >> 5;
    const int h    = tid >> 6;
    const int q    = tid & 3;              // quarter within 4-lane group
    const int gbase = lane & ~3;           // group base lane

    __shared__ float s_item[RN_D];
    __shared__ float s_v[RN_NREL][RN_D];   // 2KB V slice for this b
    __shared__ float s_red[4];
    __shared__ float s_part[4][RN_D];

    // load item embedding + V[b] slice
    if (tid < RN_D) {
        const int it = items[b];
        s_item[tid] = __ldg(ent + (size_t)it * RN_D + tid);
    }
    ((float4*)s_v)[tid] = __ldg((const float4*)(g_V + (size_t)b * (RN_NREL * RN_D)) + tid);

    // owned-memory indices (fully coalesced)
    const int gidx = (h * RN_B + b) * RN_M + (tid & 63);
    const int hidx_own = heads[gidx];
    const int ridx_own = rels[gidx];
    const int tidx_own = tails[gidx];

    __syncthreads();

    // ---- phase A: logits. Group of 4 lanes covers 4 memories; lane q loads quarter q. ----
    float part[4];
    #pragma unroll
    for (int k = 0; k < 4; k++) {
        const int src = gbase + k;  // owner lane of memory (tid&~3)+k
        const int hk  = __shfl_sync(0xFFFFFFFFu, hidx_own, src);
        const int rk  = __shfl_sync(0xFFFFFFFFu, ridx_own, src);
        const float4 hv = __ldg((const float4*)(ent + (size_t)hk * RN_D) + q);
        const float4 vv = *((const float4*)&s_v[rk][0] + q);
        part[k] = hv.x * vv.x + hv.y * vv.y + hv.z * vv.z + hv.w * vv.w;
    }
    // reduce each part[k] over the 4 lanes of the group; own memory has k == q
    #pragma unroll
    for (int k = 0; k < 4; k++) {
        part[k] += __shfl_xor_sync(0xFFFFFFFFu, part[k], 1);
        part[k] += __shfl_xor_sync(0xFFFFFFFFu, part[k], 2);
    }
    float logit = part[0];
    if (q == 1) logit = part[1];
    else if (q == 2) logit = part[2];
    else if (q == 3) logit = part[3];

    // ---- phase B: softmax over m (64 values = 2 warps per h) ----
    float mx = logit;
    #pragma unroll
    for (int o = 16; o; o >>= 1)
        mx = fmaxf(mx, __shfl_xor_sync(0xFFFFFFFFu, mx, o));
    if (lane == 0) s_red[warp] = mx;
    __syncthreads();
    mx = fmaxf(s_red[h * 2], s_red[h * 2 + 1]);

    const float p = __expf(logit - mx);
    float sm = p;
    #pragma unroll
    for (int o = 16; o; o >>= 1)
        sm += __shfl_xor_sync(0xFFFFFFFFu, sm, o);
    __syncthreads();
    if (lane == 0) s_red[warp] = sm;
    __syncthreads();
    sm = s_red[h * 2] + s_red[h * 2 + 1];
    const float pi = p / sm;

    // ---- phase C: weighted tails, cooperative quarters ----
    float4 acc = make_float4(0.f, 0.f, 0.f, 0.f);
    #pragma unroll
    for (int k = 0; k < 4; k++) {
        const int src = gbase + k;
        const int tk  = __shfl_sync(0xFFFFFFFFu, tidx_own, src);
        const float pk = __shfl_sync(0xFFFFFFFFu, pi, src);
        const float4 tv = __ldg((const float4*)(ent + (size_t)tk * RN_D) + q);
        acc.x = fmaf(pk, tv.x, acc.x);
        acc.y = fmaf(pk, tv.y, acc.y);
        acc.z = fmaf(pk, tv.z, acc.z);
        acc.w = fmaf(pk, tv.w, acc.w);
    }
    // reduce across the 8 groups of the warp (lanes with same q, stride 4)
    #pragma unroll
    for (int o = 4; o <= 16; o <<= 1) {
        acc.x += __shfl_xor_sync(0xFFFFFFFFu, acc.x, o);
        acc.y += __shfl_xor_sync(0xFFFFFFFFu, acc.y, o);
        acc.z += __shfl_xor_sync(0xFFFFFFFFu, acc.z, o);
        acc.w += __shfl_xor_sync(0xFFFFFFFFu, acc.w, o);
    }
    if (lane < 4)
        *((float4*)&s_part[warp][0] + lane) = acc;   // lane == quarter
    __syncthreads();

    // ---- final dot + sigmoid (first 16 threads, warp 0) ----
    if (tid < RN_D) {
        const float u = s_part[0][tid] + s_part[1][tid]
                      + s_part[2][tid] + s_part[3][tid];
        float v = u * s_item[tid];
        v += __shfl_xor_sync(0x0000FFFFu, v, 1);
        v += __shfl_xor_sync(0x0000FFFFu, v, 2);
        v += __shfl_xor_sync(0x0000FFFFu, v, 4);
        v += __shfl_xor_sync(0x0000FFFFu, v, 8);
        if (tid == 0)
            out[b] = 1.f / (1.f + __expf(-v));
    }
}

extern "C" void kernel_launch(void* const* d_in, const int* in_sizes, int n_in,
                              void* d_out, int out_size)
{
    const int*   items = (const int*)  d_in[0];
    const int*   heads = (const int*)  d_in[1];
    const int*   rels  = (const int*)  d_in[2];
    const int*   tails = (const int*)  d_in[3];
    const float* ent   = (const float*)d_in[4];
    const float* rel   = (const float*)d_in[5];
    float*       out   = (float*)      d_out;

    vprep_kernel<<<RN_B / RN_BPB, 128>>>(items, ent, rel);
    ripple_main<<<RN_B, 128>>>(items, heads, rels, tails, ent, out);
}